// round 1
// baseline (speedup 1.0000x reference)
#include <cuda_runtime.h>
#include <cuda_bf16.h>
#include <cstdint>

// Problem constants (fixed by reference setup_inputs)
// B=16, T=16 (Tm1=15), K=32, Do=128, H=256
#define NBT   240            // B * (T-1)
#define NOBJ  32             // K
#define DOBJ  128            // Do
#define NH    256            // H
#define MROWS (NBT * NOBJ)   // 7680 object rows

// Scratch: U = O @ W1[:, :128]^T,  Vp = O @ W1[:, 128:]^T + b1
__device__ float g_U [MROWS * NH];
__device__ float g_Vp[MROWS * NH];

// ---------------------------------------------------------------------------
// Kernel 1: GEMM  M=7680, N=512 (cols 0..255 -> U, 256..511 -> V+b1), K=128
// A[m,k] = O[m,k] (gathered from sets_of_objects[:,1:]),
// B[k,o'] = W1[(o'&255), (o'>=256 ? 128 : 0) + k]
// 128x128 CTA tile, 8x8 per-thread micro tile, K-chunks of 16.
// ---------------------------------------------------------------------------
__global__ __launch_bounds__(256, 2)
void gemm1_kernel(const float* __restrict__ X, const float* __restrict__ W1,
                  const float* __restrict__ b1) {
    __shared__ float As[16 * 132];   // [kk][m] transposed
    __shared__ float Bs[16 * 132];   // [kk][n]

    const int tid   = threadIdx.x;
    const int tx    = tid & 15;
    const int ty    = tid >> 4;
    const int mtile = blockIdx.y;    // 0..59
    const int ntile = blockIdx.x;    // 0..3
    const int n0    = ntile * 128;

    float acc[8][8];
#pragma unroll
    for (int i = 0; i < 8; i++)
#pragma unroll
        for (int j = 0; j < 8; j++) acc[i][j] = 0.0f;

    for (int kc = 0; kc < DOBJ; kc += 16) {
        // Load A tile: 128 rows x 16 k  (512 float4 slots)
#pragma unroll
        for (int q = 0; q < 2; q++) {
            int idx = tid * 2 + q;
            int row = idx >> 2;
            int kq  = idx & 3;
            int m   = mtile * 128 + row;
            int bt  = m >> 5;
            int i   = m & 31;
            int b   = bt / 15;
            int t   = bt - b * 15;
            const float4 v = *(const float4*)(
                X + (size_t)((b * 16 + t + 1) * 32 + i) * DOBJ + kc + kq * 4);
            As[(kq * 4 + 0) * 132 + row] = v.x;
            As[(kq * 4 + 1) * 132 + row] = v.y;
            As[(kq * 4 + 2) * 132 + row] = v.z;
            As[(kq * 4 + 3) * 132 + row] = v.w;
        }
        // Load B tile: 16 k x 128 n from W1
#pragma unroll
        for (int q = 0; q < 2; q++) {
            int idx = tid * 2 + q;
            int col = idx >> 2;
            int kq  = idx & 3;
            int o   = n0 + col;
            int base = (o & 255) * 256 + ((o >> 8) << 7);
            const float4 v = *(const float4*)(W1 + base + kc + kq * 4);
            Bs[(kq * 4 + 0) * 132 + col] = v.x;
            Bs[(kq * 4 + 1) * 132 + col] = v.y;
            Bs[(kq * 4 + 2) * 132 + col] = v.z;
            Bs[(kq * 4 + 3) * 132 + col] = v.w;
        }
        __syncthreads();
#pragma unroll
        for (int kk = 0; kk < 16; kk++) {
            float a[8], bb[8];
            *(float4*)(a)      = *(const float4*)(&As[kk * 132 + ty * 8]);
            *(float4*)(a + 4)  = *(const float4*)(&As[kk * 132 + ty * 8 + 4]);
            *(float4*)(bb)     = *(const float4*)(&Bs[kk * 132 + tx * 8]);
            *(float4*)(bb + 4) = *(const float4*)(&Bs[kk * 132 + tx * 8 + 4]);
#pragma unroll
            for (int im = 0; im < 8; im++)
#pragma unroll
                for (int in = 0; in < 8; in++)
                    acc[im][in] = fmaf(a[im], bb[in], acc[im][in]);
        }
        __syncthreads();
    }

    if (ntile < 2) {
#pragma unroll
        for (int im = 0; im < 8; im++) {
            int m = mtile * 128 + ty * 8 + im;
            float* dst = g_U + (size_t)m * NH + n0 + tx * 8;
            *(float4*)(dst)     = make_float4(acc[im][0], acc[im][1], acc[im][2], acc[im][3]);
            *(float4*)(dst + 4) = make_float4(acc[im][4], acc[im][5], acc[im][6], acc[im][7]);
        }
    } else {
        int ov = n0 - 256 + tx * 8;
        float bb1[8];
#pragma unroll
        for (int j = 0; j < 8; j++) bb1[j] = b1[ov + j];
#pragma unroll
        for (int im = 0; im < 8; im++) {
            int m = mtile * 128 + ty * 8 + im;
            float* dst = g_Vp + (size_t)m * NH + ov;
            *(float4*)(dst)     = make_float4(acc[im][0] + bb1[0], acc[im][1] + bb1[1],
                                              acc[im][2] + bb1[2], acc[im][3] + bb1[3]);
            *(float4*)(dst + 4) = make_float4(acc[im][4] + bb1[4], acc[im][5] + bb1[5],
                                              acc[im][6] + bb1[6], acc[im][7] + bb1[7]);
        }
    }
}

// ---------------------------------------------------------------------------
// Kernel 2: per (b,t): h[p=(i,j),k] = relu(U[i,k] + Vp[j,k]) generated in smem,
// then e = relu(h @ W2^T + b2). CTA: 128(M) x 128(N), K-chunks of 16.
// Grid: (ntile=2, mtile=8, bt=240)
// ---------------------------------------------------------------------------
__global__ __launch_bounds__(256, 2)
void gemm2_kernel(const float* __restrict__ W2, const float* __restrict__ b2,
                  float* __restrict__ out_e) {
    extern __shared__ float sm[];
    float* sV = sm;                  // 32 x 256, stride 257
    float* sU = sV + 32 * 257;       // 4 x 256
    float* As = sU + 4 * 256;        // 16 x 132  (h tile, [kk][p])
    float* Bs = As + 16 * 132;       // 16 x 132  (W2^T tile, [kk][n])

    const int tid   = threadIdx.x;
    const int tx    = tid & 15;
    const int ty    = tid >> 4;
    const int ntile = blockIdx.x;    // 0..1
    const int mtile = blockIdx.y;    // 0..7
    const int bt    = blockIdx.z;    // 0..239
    const int n0    = ntile * 128;

    // Stage V' (all 32 rows) with pad-257 layout
    const float* Vg = g_Vp + (size_t)bt * NOBJ * NH;
#pragma unroll
    for (int q = 0; q < 8; q++) {
        int fidx = tid + q * 256;            // float4 index 0..2047
        float4 v = ((const float4*)Vg)[fidx];
        int row = fidx >> 6;                 // 64 float4 per 256-float row
        int col = (fidx & 63) * 4;
        float* d = sV + row * 257 + col;
        d[0] = v.x; d[1] = v.y; d[2] = v.z; d[3] = v.w;
    }
    // Stage U rows for this M tile (4 rows of 256)
    {
        const float* Ug = g_U + ((size_t)bt * NOBJ + mtile * 4) * NH;
        ((float4*)sU)[tid] = ((const float4*)Ug)[tid];
    }
    __syncthreads();

    float acc[8][8];
#pragma unroll
    for (int i = 0; i < 8; i++)
#pragma unroll
        for (int j = 0; j < 8; j++) acc[i][j] = 0.0f;

    const int p_me  = tid & 127;     // local pair row this thread fills in As
    const int khalf = tid >> 7;      // 0/1
    const int iu    = (p_me >> 5) * 256;   // U row offset (broadcast per warp)
    const int jv    = (p_me & 31) * 257;   // V row offset (conflict-free)

    for (int kc = 0; kc < NH; kc += 16) {
        // Materialize h tile: As[kk][p] = relu(U[i, kc+kk] + Vp[j, kc+kk])
#pragma unroll
        for (int q = 0; q < 8; q++) {
            int kk = q * 2 + khalf;
            float x = sU[iu + kc + kk] + sV[jv + kc + kk];
            As[kk * 132 + p_me] = fmaxf(x, 0.0f);
        }
        // Load W2^T tile: Bs[kk][n] = W2[n0+n][kc+kk]  (L2-resident)
#pragma unroll
        for (int q = 0; q < 2; q++) {
            int idx = tid * 2 + q;
            int col = idx >> 2;
            int kq  = idx & 3;
            const float4 v = *(const float4*)(W2 + (size_t)(n0 + col) * NH + kc + kq * 4);
            Bs[(kq * 4 + 0) * 132 + col] = v.x;
            Bs[(kq * 4 + 1) * 132 + col] = v.y;
            Bs[(kq * 4 + 2) * 132 + col] = v.z;
            Bs[(kq * 4 + 3) * 132 + col] = v.w;
        }
        __syncthreads();
#pragma unroll
        for (int kk = 0; kk < 16; kk++) {
            float a[8], bb[8];
            *(float4*)(a)      = *(const float4*)(&As[kk * 132 + ty * 8]);
            *(float4*)(a + 4)  = *(const float4*)(&As[kk * 132 + ty * 8 + 4]);
            *(float4*)(bb)     = *(const float4*)(&Bs[kk * 132 + tx * 8]);
            *(float4*)(bb + 4) = *(const float4*)(&Bs[kk * 132 + tx * 8 + 4]);
#pragma unroll
            for (int im = 0; im < 8; im++)
#pragma unroll
                for (int in = 0; in < 8; in++)
                    acc[im][in] = fmaf(a[im], bb[in], acc[im][in]);
        }
        __syncthreads();
    }

    // Epilogue: e = relu(acc + b2)
    float bb2[8];
#pragma unroll
    for (int j = 0; j < 8; j++) bb2[j] = b2[n0 + tx * 8 + j];
    size_t base = ((size_t)bt * 1024 + mtile * 128) * NH;
#pragma unroll
    for (int im = 0; im < 8; im++) {
        int p = ty * 8 + im;
        float* dst = out_e + base + (size_t)p * NH + n0 + tx * 8;
        float4 r0, r1;
        r0.x = fmaxf(acc[im][0] + bb2[0], 0.0f);
        r0.y = fmaxf(acc[im][1] + bb2[1], 0.0f);
        r0.z = fmaxf(acc[im][2] + bb2[2], 0.0f);
        r0.w = fmaxf(acc[im][3] + bb2[3], 0.0f);
        r1.x = fmaxf(acc[im][4] + bb2[4], 0.0f);
        r1.y = fmaxf(acc[im][5] + bb2[5], 0.0f);
        r1.z = fmaxf(acc[im][6] + bb2[6], 0.0f);
        r1.w = fmaxf(acc[im][7] + bb2[7], 0.0f);
        *(float4*)(dst)     = r0;
        *(float4*)(dst + 4) = r1;
    }
}

// ---------------------------------------------------------------------------
// Aux: s_i = clip(sum_d O[bt,i,d],0,1);  all_is_obj[bt,p=(i,j)] = clip(s_i*s_j*(t+1),0,1)
// ---------------------------------------------------------------------------
__global__ void aux_kernel(const float* __restrict__ X, float* __restrict__ out_a) {
    __shared__ float partial[256];
    __shared__ float s[32];
    const int bt = blockIdx.x;
    const int b  = bt / 15;
    const int t  = bt - b * 15;
    const float* base = X + (size_t)((b * 16 + t + 1) * 32) * DOBJ;
    const int tid = threadIdx.x;

    {   // 8 threads per object row, 16 elements each
        int i = tid >> 3, part = tid & 7;
        const float* r = base + i * DOBJ + part * 16;
        float ssum = 0.0f;
#pragma unroll
        for (int k = 0; k < 16; k++) ssum += r[k];
        partial[tid] = ssum;
    }
    __syncthreads();
    if (tid < 32) {
        float tot = 0.0f;
#pragma unroll
        for (int j = 0; j < 8; j++) tot += partial[tid * 8 + j];
        s[tid] = fminf(fmaxf(tot, 0.0f), 1.0f);
    }
    __syncthreads();
    float tc = (float)(t + 1);
#pragma unroll
    for (int q = 0; q < 4; q++) {
        int p = tid + q * 256;
        float v = s[p >> 5] * s[p & 31] * tc;
        out_a[(size_t)bt * 1024 + p] = fminf(fmaxf(v, 0.0f), 1.0f);
    }
}

// ---------------------------------------------------------------------------
extern "C" void kernel_launch(void* const* d_in, const int* in_sizes, int n_in,
                              void* d_out, int out_size) {
    const float* X  = (const float*)d_in[0];  // sets_of_objects (16,16,32,128)
    const float* W1 = (const float*)d_in[1];  // (256, 256)
    const float* b1 = (const float*)d_in[2];  // (256,)
    const float* W2 = (const float*)d_in[3];  // (256, 256)
    const float* b2 = (const float*)d_in[4];  // (256,)
    float* out = (float*)d_out;

    // Output layout: e (240*1024*256 floats) then all_is_obj (240*1024 floats)
    size_t e_elems = (size_t)out_size - (size_t)NBT * 1024;

    const int smem2 = (32 * 257 + 4 * 256 + 16 * 132 + 16 * 132) * sizeof(float); // 53888
    cudaFuncSetAttribute(gemm2_kernel, cudaFuncAttributeMaxDynamicSharedMemorySize, smem2);

    gemm1_kernel<<<dim3(4, 60), 256>>>(X, W1, b1);
    gemm2_kernel<<<dim3(2, 8, NBT), 256, smem2>>>(W2, b2, out);
    aux_kernel<<<NBT, 256>>>(X, out + e_elems);
}

// round 4
// speedup vs baseline: 3.9302x; 3.9302x over previous
#include <cuda_runtime.h>
#include <cuda_fp16.h>
#include <cstdint>

// Problem constants: B=16, T=16 (Tm1=15), K=32, Do=128, H=256
#define NBT   240
#define NOBJ  32
#define DOBJ  128
#define NH    256
#define MROWS (NBT * NOBJ)   // 7680

// Scratch
__device__ float g_U [MROWS * NH];
__device__ float g_Vp[MROWS * NH];
// Pre-converted fp16, SW128-swizzled W2 chunk images: [nhalf(2)][chunk(4)][128 rows x 64 halfs]
__device__ __align__(16) unsigned char g_W2h[2 * 4 * 16384];

__device__ __forceinline__ uint32_t sw128(uint32_t off) { return off ^ ((off >> 3) & 0x70); }
__device__ __forceinline__ uint32_t smem_u32(const void* p) {
    uint32_t a;
    asm("{ .reg .u64 t; cvta.to.shared.u64 t, %1; cvt.u32.u64 %0, t; }" : "=r"(a) : "l"(p));
    return a;
}

#define LDSM_X4(r0, r1, r2, r3, addr) \
    asm volatile("ldmatrix.sync.aligned.m8n8.x4.shared.b16 {%0,%1,%2,%3}, [%4];" \
        : "=r"(r0), "=r"(r1), "=r"(r2), "=r"(r3) : "r"(addr))
#define MMA16816(d, a, b) \
    asm volatile("mma.sync.aligned.m16n8k16.row.col.f32.f16.f16.f32 " \
        "{%0,%1,%2,%3}, {%4,%5,%6,%7}, {%8,%9}, {%0,%1,%2,%3};" \
        : "+f"((d)[0]), "+f"((d)[1]), "+f"((d)[2]), "+f"((d)[3]) \
        : "r"((a)[0]), "r"((a)[1]), "r"((a)[2]), "r"((a)[3]), "r"((b)[0]), "r"((b)[1]))

__device__ __forceinline__ uint32_t pack2(float x0, float x1) {
    return (uint32_t)__half_as_ushort(__float2half_rn(x0)) |
           ((uint32_t)__half_as_ushort(__float2half_rn(x1)) << 16);
}

// ---------------------------------------------------------------------------
// Kernel 0: W2 -> fp16, SW128-swizzled chunk images
// ---------------------------------------------------------------------------
__global__ void wsplit_kernel(const float* __restrict__ W2) {
    int idx = blockIdx.x * 256 + threadIdx.x;   // 0..8191
    int n   = idx >> 5;                          // 0..255
    int g   = idx & 31;
    int c   = g >> 3;                            // chunk 0..3
    int k8  = (g & 7) * 8;                       // k within chunk
    const float* src = W2 + n * 256 + c * 64 + k8;
    uint32_t w[4];
#pragma unroll
    for (int q = 0; q < 4; q++) w[q] = pack2(src[q * 2], src[q * 2 + 1]);
    uint32_t sw = sw128((uint32_t)((n & 127) * 128 + k8 * 2));
    *(uint4*)(g_W2h + (n >> 7) * 65536 + c * 16384 + sw) = make_uint4(w[0], w[1], w[2], w[3]);
}

// ---------------------------------------------------------------------------
// Kernel 1: fp32 SGEMM  M=7680, N=512 (U | V+b1), K=128
// ---------------------------------------------------------------------------
__global__ __launch_bounds__(256, 2)
void gemm1_kernel(const float* __restrict__ X, const float* __restrict__ W1,
                  const float* __restrict__ b1) {
    __shared__ float As[16 * 132];
    __shared__ float Bs[16 * 132];
    const int tid = threadIdx.x, tx = tid & 15, ty = tid >> 4;
    const int mtile = blockIdx.y, ntile = blockIdx.x, n0 = ntile * 128;
    float acc[8][8];
#pragma unroll
    for (int i = 0; i < 8; i++)
#pragma unroll
        for (int j = 0; j < 8; j++) acc[i][j] = 0.0f;
    for (int kc = 0; kc < DOBJ; kc += 16) {
#pragma unroll
        for (int q = 0; q < 2; q++) {
            int idx = tid * 2 + q, row = idx >> 2, kq = idx & 3;
            int m = mtile * 128 + row, bt = m >> 5, i = m & 31;
            int b = bt / 15, t = bt - b * 15;
            const float4 v = *(const float4*)(X + (size_t)((b * 16 + t + 1) * 32 + i) * DOBJ + kc + kq * 4);
            As[(kq * 4 + 0) * 132 + row] = v.x; As[(kq * 4 + 1) * 132 + row] = v.y;
            As[(kq * 4 + 2) * 132 + row] = v.z; As[(kq * 4 + 3) * 132 + row] = v.w;
        }
#pragma unroll
        for (int q = 0; q < 2; q++) {
            int idx = tid * 2 + q, col = idx >> 2, kq = idx & 3;
            int o = n0 + col, base = (o & 255) * 256 + ((o >> 8) << 7);
            const float4 v = *(const float4*)(W1 + base + kc + kq * 4);
            Bs[(kq * 4 + 0) * 132 + col] = v.x; Bs[(kq * 4 + 1) * 132 + col] = v.y;
            Bs[(kq * 4 + 2) * 132 + col] = v.z; Bs[(kq * 4 + 3) * 132 + col] = v.w;
        }
        __syncthreads();
#pragma unroll
        for (int kk = 0; kk < 16; kk++) {
            float a[8], bb[8];
            *(float4*)(a)     = *(const float4*)(&As[kk * 132 + ty * 8]);
            *(float4*)(a + 4) = *(const float4*)(&As[kk * 132 + ty * 8 + 4]);
            *(float4*)(bb)     = *(const float4*)(&Bs[kk * 132 + tx * 8]);
            *(float4*)(bb + 4) = *(const float4*)(&Bs[kk * 132 + tx * 8 + 4]);
#pragma unroll
            for (int im = 0; im < 8; im++)
#pragma unroll
                for (int in = 0; in < 8; in++)
                    acc[im][in] = fmaf(a[im], bb[in], acc[im][in]);
        }
        __syncthreads();
    }
    if (ntile < 2) {
#pragma unroll
        for (int im = 0; im < 8; im++) {
            int m = mtile * 128 + ty * 8 + im;
            float* dst = g_U + (size_t)m * NH + n0 + tx * 8;
            *(float4*)(dst)     = make_float4(acc[im][0], acc[im][1], acc[im][2], acc[im][3]);
            *(float4*)(dst + 4) = make_float4(acc[im][4], acc[im][5], acc[im][6], acc[im][7]);
        }
    } else {
        int ov = n0 - 256 + tx * 8;
        float bb1[8];
#pragma unroll
        for (int j = 0; j < 8; j++) bb1[j] = b1[ov + j];
#pragma unroll
        for (int im = 0; im < 8; im++) {
            int m = mtile * 128 + ty * 8 + im;
            float* dst = g_Vp + (size_t)m * NH + ov;
            *(float4*)(dst)     = make_float4(acc[im][0] + bb1[0], acc[im][1] + bb1[1],
                                              acc[im][2] + bb1[2], acc[im][3] + bb1[3]);
            *(float4*)(dst + 4) = make_float4(acc[im][4] + bb1[4], acc[im][5] + bb1[5],
                                              acc[im][6] + bb1[6], acc[im][7] + bb1[7]);
        }
    }
}

// ---------------------------------------------------------------------------
// Kernel 2: GEMM2 via mma.sync fp16 (fp32 accum).
// Grid (nh=2, mtile=8, bt=240), 256 threads. CTA tile: 128 pairs x 128 outs.
// ---------------------------------------------------------------------------
#define OFF_A   0        // 128 x 64 half, SW128  (16384 B)
#define OFF_B   16384    // 128 x 64 half, SW128  (16384 B)
#define OFF_V   32768    // 32 x 257 fp32         (32896 B)
#define OFF_U   65664    // 4 x 256 fp32          (4096 B)
#define OFF_B2  69760    // 128 fp32              (512 B)
#define SMEM2   70272

__global__ __launch_bounds__(256, 2)
void gemm2_mma(const float* __restrict__ b2, float* __restrict__ out_e) {
    extern __shared__ __align__(1024) unsigned char smem[];
    const int tid = threadIdx.x, lane = tid & 31, wid = tid >> 5;
    const int nh = blockIdx.x, mtile = blockIdx.y, bt = blockIdx.z;

    float* sV  = (float*)(smem + OFF_V);
    float* sU  = (float*)(smem + OFF_U);
    float* sb2 = (float*)(smem + OFF_B2);

    // Stage V' (32x256, pad-257), U (4 rows for this mtile), b2 half
    {
        const float* Vg = g_Vp + (size_t)bt * NOBJ * NH;
#pragma unroll
        for (int q = 0; q < 8; q++) {
            int fidx = tid + q * 256;
            float4 v = ((const float4*)Vg)[fidx];
            int row = fidx >> 6, col = (fidx & 63) * 4;
            float* d = sV + row * 257 + col;
            d[0] = v.x; d[1] = v.y; d[2] = v.z; d[3] = v.w;
        }
        const float* Ug = g_U + ((size_t)bt * NOBJ + mtile * 4) * NH;
        ((float4*)sU)[tid] = ((const float4*)Ug)[tid];
        if (tid < 32) ((float4*)sb2)[tid] = ((const float4*)(b2 + nh * 128))[tid];
    }
    __syncthreads();

    const uint32_t sA = smem_u32(smem);
    const uint32_t sB = sA + OFF_B;

    float acc[2][8][4];
#pragma unroll
    for (int mt = 0; mt < 2; mt++)
#pragma unroll
        for (int nt = 0; nt < 8; nt++)
#pragma unroll
            for (int q = 0; q < 4; q++) acc[mt][nt][q] = 0.0f;

    const int m0w = (wid & 3) * 32;
    const int n0w = (wid >> 2) * 64;
    // gen-A duty: one row, half of k
    const int r  = tid & 127;
    const int kh = tid >> 7;
    const float* urow_base = sU + (r >> 5) * 256 + kh * 32;
    const float* vrow_base = sV + (r & 31) * 257 + kh * 32;

    const uint4* gB = (const uint4*)(g_W2h + nh * 65536);

    for (int c = 0; c < 4; c++) {
        // ---- generate A chunk: h = relu(U_i + V_j) -> fp16, swizzled ----
        {
            const float* urow = urow_base + c * 64;
            const float* vrow = vrow_base + c * 64;
#pragma unroll
            for (int g = 0; g < 4; g++) {
                float us[8];
                *(float4*)(us)     = *(const float4*)(urow + g * 8);
                *(float4*)(us + 4) = *(const float4*)(urow + g * 8 + 4);
                uint32_t w[4];
#pragma unroll
                for (int q = 0; q < 4; q++) {
                    float x0 = fmaxf(us[q * 2]     + vrow[g * 8 + q * 2],     0.0f);
                    float x1 = fmaxf(us[q * 2 + 1] + vrow[g * 8 + q * 2 + 1], 0.0f);
                    w[q] = pack2(x0, x1);
                }
                uint32_t off = sw128((uint32_t)(r * 128 + kh * 64 + g * 16));
                *(uint4*)(smem + off) = make_uint4(w[0], w[1], w[2], w[3]);
            }
        }
        // ---- copy B chunk (pre-swizzled fp16 image, L2-resident) ----
        {
            uint4* dB = (uint4*)(smem + OFF_B);
#pragma unroll
            for (int q = 0; q < 4; q++)
                dB[tid + q * 256] = gB[c * 1024 + tid + q * 256];
        }
        __syncthreads();

        // ---- mma over this 64-k chunk ----
#pragma unroll
        for (int ks = 0; ks < 4; ks++) {
            uint32_t afr[2][4], bfr[8][2];
            int abyte = ks * 32 + ((lane >> 4) << 4);
            int arow  = m0w + (lane & 15);
            uint32_t aaddr0 = sA + sw128((uint32_t)(arow * 128 + abyte));
            uint32_t aaddr1 = sA + sw128((uint32_t)((arow + 16) * 128 + abyte));
            LDSM_X4(afr[0][0], afr[0][1], afr[0][2], afr[0][3], aaddr0);
            LDSM_X4(afr[1][0], afr[1][1], afr[1][2], afr[1][3], aaddr1);

            // B stored [n][k] row-major == col-major kxn: NON-trans ldmatrix
            int nr  = n0w + ((lane >> 4) << 3) + (lane & 7);
            int kb2 = ks * 32 + (((lane >> 3) & 1) << 4);
#pragma unroll
            for (int ntp = 0; ntp < 4; ntp++) {
                uint32_t baddr = sB + sw128((uint32_t)((nr + ntp * 16) * 128 + kb2));
                LDSM_X4(bfr[ntp * 2][0], bfr[ntp * 2][1],
                        bfr[ntp * 2 + 1][0], bfr[ntp * 2 + 1][1], baddr);
            }
#pragma unroll
            for (int mt = 0; mt < 2; mt++)
#pragma unroll
                for (int nt = 0; nt < 8; nt++)
                    MMA16816(acc[mt][nt], afr[mt], bfr[nt]);
        }
        if (c < 3) __syncthreads();
    }

    // ---- epilogue: e = relu(acc + b2) ----
    const size_t rowbase = (size_t)bt * 1024 + mtile * 128;
#pragma unroll
    for (int mt = 0; mt < 2; mt++) {
#pragma unroll
        for (int hp = 0; hp < 2; hp++) {
            int rl = m0w + mt * 16 + hp * 8 + (lane >> 2);
            float* dst = out_e + (rowbase + rl) * 256 + nh * 128 + (lane & 3) * 2;
#pragma unroll
            for (int nt = 0; nt < 8; nt++) {
                int nc = n0w + nt * 8 + (lane & 3) * 2;
                float2 o;
                o.x = fmaxf(acc[mt][nt][hp * 2]     + sb2[nc],     0.0f);
                o.y = fmaxf(acc[mt][nt][hp * 2 + 1] + sb2[nc + 1], 0.0f);
                *(float2*)(dst + n0w + nt * 8) = o;
            }
        }
    }
}

// ---------------------------------------------------------------------------
// Aux: all_is_obj
// ---------------------------------------------------------------------------
__global__ void aux_kernel(const float* __restrict__ X, float* __restrict__ out_a) {
    __shared__ float partial[256];
    __shared__ float s[32];
    const int bt = blockIdx.x;
    const int b = bt / 15, t = bt - b * 15;
    const float* base = X + (size_t)((b * 16 + t + 1) * 32) * DOBJ;
    const int tid = threadIdx.x;
    {
        int i = tid >> 3, part = tid & 7;
        const float* r = base + i * DOBJ + part * 16;
        float ssum = 0.0f;
#pragma unroll
        for (int k = 0; k < 16; k++) ssum += r[k];
        partial[tid] = ssum;
    }
    __syncthreads();
    if (tid < 32) {
        float tot = 0.0f;
#pragma unroll
        for (int j = 0; j < 8; j++) tot += partial[tid * 8 + j];
        s[tid] = fminf(fmaxf(tot, 0.0f), 1.0f);
    }
    __syncthreads();
    float tc = (float)(t + 1);
#pragma unroll
    for (int q = 0; q < 4; q++) {
        int p = tid + q * 256;
        float v = s[p >> 5] * s[p & 31] * tc;
        out_a[(size_t)bt * 1024 + p] = fminf(fmaxf(v, 0.0f), 1.0f);
    }
}

// ---------------------------------------------------------------------------
extern "C" void kernel_launch(void* const* d_in, const int* in_sizes, int n_in,
                              void* d_out, int out_size) {
    const float* X  = (const float*)d_in[0];
    const float* W1 = (const float*)d_in[1];
    const float* b1 = (const float*)d_in[2];
    const float* W2 = (const float*)d_in[3];
    const float* b2 = (const float*)d_in[4];
    float* out = (float*)d_out;

    size_t e_elems = (size_t)out_size - (size_t)NBT * 1024;

    cudaFuncSetAttribute(gemm2_mma, cudaFuncAttributeMaxDynamicSharedMemorySize, SMEM2);

    wsplit_kernel<<<32, 256>>>(W2);
    gemm1_kernel<<<dim3(4, 60), 256>>>(X, W1, b1);
    gemm2_mma<<<dim3(2, 8, NBT), 256, SMEM2>>>(b2, out);
    aux_kernel<<<NBT, 256>>>(X, out + e_elems);
}

// round 5
// speedup vs baseline: 4.6061x; 1.1720x over previous
#include <cuda_runtime.h>
#include <cuda_fp16.h>
#include <cstdint>

// Problem constants: B=16, T=16 (Tm1=15), K=32, Do=128, H=256
#define NBT   240
#define NOBJ  32
#define DOBJ  128
#define NH    256
#define MROWS (NBT * NOBJ)   // 7680

// Scratch
__device__ float g_U [MROWS * NH];
__device__ float g_Vp[MROWS * NH];
__device__ float g_S [MROWS];              // clipped per-object row sums
// fp16 SW128-swizzled images (each image = 128 rows x 64 halfs = 16KB)
__device__ __align__(16) unsigned char g_W2h[2 * 4 * 16384];   // [nh][4 k-imgs]
__device__ __align__(16) unsigned char g_Xh [60 * 2 * 16384];  // [mtile][2 k-imgs]
__device__ __align__(16) unsigned char g_W1h[4 * 2 * 16384];   // [ntile][2 k-imgs]

__device__ __forceinline__ uint32_t sw128(uint32_t off) { return off ^ ((off >> 3) & 0x70); }
__device__ __forceinline__ uint32_t smem_u32(const void* p) {
    uint32_t a;
    asm("{ .reg .u64 t; cvta.to.shared.u64 t, %1; cvt.u32.u64 %0, t; }" : "=r"(a) : "l"(p));
    return a;
}

#define LDSM_X4(r0, r1, r2, r3, addr) \
    asm volatile("ldmatrix.sync.aligned.m8n8.x4.shared.b16 {%0,%1,%2,%3}, [%4];" \
        : "=r"(r0), "=r"(r1), "=r"(r2), "=r"(r3) : "r"(addr))
#define MMA16816(d, a, b) \
    asm volatile("mma.sync.aligned.m16n8k16.row.col.f32.f16.f16.f32 " \
        "{%0,%1,%2,%3}, {%4,%5,%6,%7}, {%8,%9}, {%0,%1,%2,%3};" \
        : "+f"((d)[0]), "+f"((d)[1]), "+f"((d)[2]), "+f"((d)[3]) \
        : "r"((a)[0]), "r"((a)[1]), "r"((a)[2]), "r"((a)[3]), "r"((b)[0]), "r"((b)[1]))
#define CP_ASYNC16(dst, src) \
    asm volatile("cp.async.cg.shared.global [%0], [%1], 16;" :: "r"((uint32_t)(dst)), "l"(src))
#define CP_COMMIT() asm volatile("cp.async.commit_group;" ::: "memory")
#define CP_WAIT0()  asm volatile("cp.async.wait_group 0;" ::: "memory")

__device__ __forceinline__ uint32_t packh2(float x0, float x1) {
    __half2 h = __float22half2_rn(make_float2(x0, x1));
    return reinterpret_cast<uint32_t&>(h);
}

// ---------------------------------------------------------------------------
// conv_x: gather X (rows t>=1) -> fp16 swizzled images; fused clipped row sums.
// 480 blocks x 256. Each thread: 8 k of one object row.
// ---------------------------------------------------------------------------
__global__ void conv_x_kernel(const float* __restrict__ X) {
    int idx = blockIdx.x * 256 + threadIdx.x;  // 0..122879
    int m  = idx >> 4;                          // 0..7679
    int g  = idx & 15;
    int kh = g >> 3, k8 = (g & 7) * 8;
    int bt = m >> 5, i = m & 31;
    int b  = bt / 15, t = bt - b * 15;
    const float* src = X + (size_t)((b * 16 + t + 1) * 32 + i) * DOBJ + kh * 64 + k8;
    float4 v0 = *(const float4*)(src);
    float4 v1 = *(const float4*)(src + 4);
    uint4 w;
    w.x = packh2(v0.x, v0.y); w.y = packh2(v0.z, v0.w);
    w.z = packh2(v1.x, v1.y); w.w = packh2(v1.z, v1.w);
    *(uint4*)(g_Xh + (m >> 7) * 32768 + kh * 16384 + sw128((uint32_t)((m & 127) * 128 + k8 * 2))) = w;
    // fused row sum over the 16 threads of this row
    float ssum = v0.x + v0.y + v0.z + v0.w + v1.x + v1.y + v1.z + v1.w;
#pragma unroll
    for (int off = 8; off >= 1; off >>= 1)
        ssum += __shfl_xor_sync(0xFFFFFFFF, ssum, off, 32);
    if (g == 0) g_S[m] = fminf(fmaxf(ssum, 0.0f), 1.0f);
}

// ---------------------------------------------------------------------------
// conv_w1: W1 -> fp16 swizzled images. B[k][o'] = W1[o'&255][(o'>=256?128:0)+k]
// ---------------------------------------------------------------------------
__global__ void conv_w1_kernel(const float* __restrict__ W1) {
    int idx = blockIdx.x * 256 + threadIdx.x;  // 0..8191
    int op = idx >> 4;                          // 0..511
    int g  = idx & 15;
    int kh = g >> 3, k8 = (g & 7) * 8;
    const float* src = W1 + (op & 255) * 256 + ((op >= 256) ? 128 : 0) + kh * 64 + k8;
    float4 v0 = *(const float4*)(src);
    float4 v1 = *(const float4*)(src + 4);
    uint4 w;
    w.x = packh2(v0.x, v0.y); w.y = packh2(v0.z, v0.w);
    w.z = packh2(v1.x, v1.y); w.w = packh2(v1.z, v1.w);
    int ntile = op >> 7, n = op & 127;
    *(uint4*)(g_W1h + ntile * 32768 + kh * 16384 + sw128((uint32_t)(n * 128 + k8 * 2))) = w;
}

// ---------------------------------------------------------------------------
// wsplit: W2 -> fp16 swizzled images [nh][chunk c: k in [c*64,(c+1)*64)]
// ---------------------------------------------------------------------------
__global__ void wsplit_kernel(const float* __restrict__ W2) {
    int idx = blockIdx.x * 256 + threadIdx.x;   // 0..8191
    int n   = idx >> 5;                          // 0..255
    int g   = idx & 31;
    int c   = g >> 3;
    int k8  = (g & 7) * 8;
    const float* src = W2 + n * 256 + c * 64 + k8;
    float4 v0 = *(const float4*)(src);
    float4 v1 = *(const float4*)(src + 4);
    uint4 w;
    w.x = packh2(v0.x, v0.y); w.y = packh2(v0.z, v0.w);
    w.z = packh2(v1.x, v1.y); w.w = packh2(v1.z, v1.w);
    *(uint4*)(g_W2h + (n >> 7) * 65536 + c * 16384 + sw128((uint32_t)((n & 127) * 128 + k8 * 2))) = w;
}

// ---------------------------------------------------------------------------
// gemm1 via mma: grid (ntile 4, mtile 60), 256 thr, CTA 128x128, K=128.
// ntile 0,1 -> U; 2,3 -> Vp (+b1)
// ---------------------------------------------------------------------------
#define G1_A    0
#define G1_B    32768
#define G1_BIAS 65536
#define G1_SMEM 66048

__global__ __launch_bounds__(256, 2)
void gemm1_mma(const float* __restrict__ b1) {
    extern __shared__ __align__(1024) unsigned char smem[];
    const int tid = threadIdx.x, lane = tid & 31, wid = tid >> 5;
    const int ntile = blockIdx.x, mtile = blockIdx.y;
    const uint32_t sA = smem_u32(smem);
    const uint32_t sB = sA + G1_B;

    const uint4* gA = (const uint4*)(g_Xh)  + (size_t)mtile * 2048;
    const uint4* gB = (const uint4*)(g_W1h) + (size_t)ntile * 2048;
#pragma unroll
    for (int q = 0; q < 8; q++) {
        int s = tid + q * 256;
        CP_ASYNC16(sA + s * 16, gA + s);
        CP_ASYNC16(sB + s * 16, gB + s);
    }
    CP_COMMIT();
    if (ntile >= 2 && tid < 32)
        ((float4*)(smem + G1_BIAS))[tid] = ((const float4*)(b1 + (ntile - 2) * 128))[tid];
    CP_WAIT0();
    __syncthreads();

    float acc[2][8][4];
#pragma unroll
    for (int mt = 0; mt < 2; mt++)
#pragma unroll
        for (int nt = 0; nt < 8; nt++)
#pragma unroll
            for (int q = 0; q < 4; q++) acc[mt][nt][q] = 0.0f;

    const int m0w = (wid & 3) * 32;
    const int n0w = (wid >> 2) * 64;

#pragma unroll
    for (int ks = 0; ks < 8; ks++) {
        const int img = ks >> 2, kk = ks & 3;
        uint32_t afr[2][4], bfr[8][2];
        int abyte = kk * 32 + ((lane >> 4) << 4);
        int arow  = m0w + (lane & 15);
        uint32_t ab = sA + img * 16384;
        LDSM_X4(afr[0][0], afr[0][1], afr[0][2], afr[0][3], ab + sw128((uint32_t)(arow * 128 + abyte)));
        LDSM_X4(afr[1][0], afr[1][1], afr[1][2], afr[1][3], ab + sw128((uint32_t)((arow + 16) * 128 + abyte)));
        int nr  = n0w + ((lane >> 4) << 3) + (lane & 7);
        int kb2 = kk * 32 + (((lane >> 3) & 1) << 4);
        uint32_t bb = sB + img * 16384;
#pragma unroll
        for (int ntp = 0; ntp < 4; ntp++) {
            LDSM_X4(bfr[ntp * 2][0], bfr[ntp * 2][1],
                    bfr[ntp * 2 + 1][0], bfr[ntp * 2 + 1][1],
                    bb + sw128((uint32_t)((nr + ntp * 16) * 128 + kb2)));
        }
#pragma unroll
        for (int mt = 0; mt < 2; mt++)
#pragma unroll
            for (int nt = 0; nt < 8; nt++)
                MMA16816(acc[mt][nt], afr[mt], bfr[nt]);
    }

    const float* sBias = (const float*)(smem + G1_BIAS);
#pragma unroll
    for (int mt = 0; mt < 2; mt++) {
#pragma unroll
        for (int hp = 0; hp < 2; hp++) {
            int rl = m0w + mt * 16 + hp * 8 + (lane >> 2);
            int m  = mtile * 128 + rl;
#pragma unroll
            for (int nt = 0; nt < 8; nt++) {
                int nc = n0w + nt * 8 + (lane & 3) * 2;
                float2 o;
                o.x = acc[mt][nt][hp * 2];
                o.y = acc[mt][nt][hp * 2 + 1];
                if (ntile < 2) {
                    *(float2*)(g_U + (size_t)m * NH + ntile * 128 + nc) = o;
                } else {
                    o.x += sBias[nc]; o.y += sBias[nc + 1];
                    *(float2*)(g_Vp + (size_t)m * NH + (ntile - 2) * 128 + nc) = o;
                }
            }
        }
    }
}

// ---------------------------------------------------------------------------
// gemm2 via mma: grid (nh 2, mtile 8, bt 240), 256 thr, CTA 128x128, K=256
// in 2 big chunks of 128 (2 images each). cp.async B overlapped with h-gen.
// ---------------------------------------------------------------------------
#define OFF_A   0        // 2 images x 16KB
#define OFF_B   32768    // 2 images x 16KB
#define OFF_V   65536    // 32 x 257 fp32 (32896)
#define OFF_U   98432    // 4 x 256 fp32  (4096)
#define OFF_B2  102528   // 128 fp32      (512)
#define SMEM2   103040

__global__ __launch_bounds__(256, 2)
void gemm2_mma(const float* __restrict__ b2, float* __restrict__ out_e) {
    extern __shared__ __align__(1024) unsigned char smem[];
    const int tid = threadIdx.x, lane = tid & 31, wid = tid >> 5;
    const int nh = blockIdx.x, mtile = blockIdx.y, bt = blockIdx.z;

    float* sV  = (float*)(smem + OFF_V);
    float* sU  = (float*)(smem + OFF_U);
    float* sb2 = (float*)(smem + OFF_B2);

    {
        const float* Vg = g_Vp + (size_t)bt * NOBJ * NH;
#pragma unroll
        for (int q = 0; q < 8; q++) {
            int fidx = tid + q * 256;
            float4 v = ((const float4*)Vg)[fidx];
            int row = fidx >> 6, col = (fidx & 63) * 4;
            float* d = sV + row * 257 + col;
            d[0] = v.x; d[1] = v.y; d[2] = v.z; d[3] = v.w;
        }
        const float* Ug = g_U + ((size_t)bt * NOBJ + mtile * 4) * NH;
        ((float4*)sU)[tid] = ((const float4*)Ug)[tid];
        if (tid < 32) ((float4*)sb2)[tid] = ((const float4*)(b2 + nh * 128))[tid];
    }
    __syncthreads();

    const uint32_t sA = smem_u32(smem);
    const uint32_t sB = sA + OFF_B;

    float acc[2][8][4];
#pragma unroll
    for (int mt = 0; mt < 2; mt++)
#pragma unroll
        for (int nt = 0; nt < 8; nt++)
#pragma unroll
            for (int q = 0; q < 4; q++) acc[mt][nt][q] = 0.0f;

    const int m0w = (wid & 3) * 32;
    const int n0w = (wid >> 2) * 64;
    const int r  = tid & 127;
    const int kh = tid >> 7;
    const float* urow0 = sU + (r >> 5) * 256 + kh * 64;
    const float* vrow0 = sV + (r & 31) * 257 + kh * 64;
    const uint4* gB = (const uint4*)(g_W2h + nh * 65536);

    for (int bc = 0; bc < 2; bc++) {
        if (bc) __syncthreads();   // previous MMA reads done before overwrite
        // async copy B (2 images)
#pragma unroll
        for (int q = 0; q < 8; q++) {
            int s = tid + q * 256;
            CP_ASYNC16(sB + s * 16, gB + bc * 2048 + s);
        }
        CP_COMMIT();
        // generate A: 64 halfs = this thread's row in image kh
        {
            const float* u = urow0 + bc * 128;
            const float* v = vrow0 + bc * 128;
            uint32_t abase = sA + kh * 16384;
#pragma unroll
            for (int g = 0; g < 8; g++) {
                float us[8];
                *(float4*)(us)     = *(const float4*)(u + g * 8);
                *(float4*)(us + 4) = *(const float4*)(u + g * 8 + 4);
                uint4 w;
                w.x = packh2(fmaxf(us[0] + v[g * 8 + 0], 0.0f), fmaxf(us[1] + v[g * 8 + 1], 0.0f));
                w.y = packh2(fmaxf(us[2] + v[g * 8 + 2], 0.0f), fmaxf(us[3] + v[g * 8 + 3], 0.0f));
                w.z = packh2(fmaxf(us[4] + v[g * 8 + 4], 0.0f), fmaxf(us[5] + v[g * 8 + 5], 0.0f));
                w.w = packh2(fmaxf(us[6] + v[g * 8 + 6], 0.0f), fmaxf(us[7] + v[g * 8 + 7], 0.0f));
                asm volatile("st.shared.v4.b32 [%0], {%1,%2,%3,%4};"
                    :: "r"(abase + sw128((uint32_t)(r * 128 + g * 16))),
                       "r"(w.x), "r"(w.y), "r"(w.z), "r"(w.w) : "memory");
            }
        }
        CP_WAIT0();
        __syncthreads();

#pragma unroll
        for (int ks = 0; ks < 8; ks++) {
            const int img = ks >> 2, kk = ks & 3;
            uint32_t afr[2][4], bfr[8][2];
            int abyte = kk * 32 + ((lane >> 4) << 4);
            int arow  = m0w + (lane & 15);
            uint32_t ab = sA + img * 16384;
            LDSM_X4(afr[0][0], afr[0][1], afr[0][2], afr[0][3], ab + sw128((uint32_t)(arow * 128 + abyte)));
            LDSM_X4(afr[1][0], afr[1][1], afr[1][2], afr[1][3], ab + sw128((uint32_t)((arow + 16) * 128 + abyte)));
            int nr  = n0w + ((lane >> 4) << 3) + (lane & 7);
            int kb2 = kk * 32 + (((lane >> 3) & 1) << 4);
            uint32_t bb = sB + img * 16384;
#pragma unroll
            for (int ntp = 0; ntp < 4; ntp++) {
                LDSM_X4(bfr[ntp * 2][0], bfr[ntp * 2][1],
                        bfr[ntp * 2 + 1][0], bfr[ntp * 2 + 1][1],
                        bb + sw128((uint32_t)((nr + ntp * 16) * 128 + kb2)));
            }
#pragma unroll
            for (int mt = 0; mt < 2; mt++)
#pragma unroll
                for (int nt = 0; nt < 8; nt++)
                    MMA16816(acc[mt][nt], afr[mt], bfr[nt]);
        }
    }

    // epilogue: e = relu(acc + b2)
    const size_t rowbase = (size_t)bt * 1024 + mtile * 128;
#pragma unroll
    for (int mt = 0; mt < 2; mt++) {
#pragma unroll
        for (int hp = 0; hp < 2; hp++) {
            int rl = m0w + mt * 16 + hp * 8 + (lane >> 2);
            float* dst = out_e + (rowbase + rl) * 256 + nh * 128 + (lane & 3) * 2;
#pragma unroll
            for (int nt = 0; nt < 8; nt++) {
                int nc = n0w + nt * 8 + (lane & 3) * 2;
                float2 o;
                o.x = fmaxf(acc[mt][nt][hp * 2]     + sb2[nc],     0.0f);
                o.y = fmaxf(acc[mt][nt][hp * 2 + 1] + sb2[nc + 1], 0.0f);
                *(float2*)(dst + n0w + nt * 8) = o;
            }
        }
    }
}

// ---------------------------------------------------------------------------
// aux2: all_is_obj from precomputed g_S
// ---------------------------------------------------------------------------
__global__ void aux2_kernel(float* __restrict__ out_a) {
    __shared__ float s[32];
    const int bt = blockIdx.x;
    const int tid = threadIdx.x;
    if (tid < 32) s[tid] = g_S[bt * 32 + tid];
    __syncthreads();
    const int t = bt - (bt / 15) * 15;
    float tc = (float)(t + 1);
#pragma unroll
    for (int q = 0; q < 4; q++) {
        int p = tid + q * 256;
        float v = s[p >> 5] * s[p & 31] * tc;
        out_a[(size_t)bt * 1024 + p] = fminf(fmaxf(v, 0.0f), 1.0f);
    }
}

// ---------------------------------------------------------------------------
extern "C" void kernel_launch(void* const* d_in, const int* in_sizes, int n_in,
                              void* d_out, int out_size) {
    const float* X  = (const float*)d_in[0];
    const float* W1 = (const float*)d_in[1];
    const float* b1 = (const float*)d_in[2];
    const float* W2 = (const float*)d_in[3];
    const float* b2 = (const float*)d_in[4];
    float* out = (float*)d_out;

    size_t e_elems = (size_t)out_size - (size_t)NBT * 1024;

    cudaFuncSetAttribute(gemm1_mma, cudaFuncAttributeMaxDynamicSharedMemorySize, G1_SMEM);
    cudaFuncSetAttribute(gemm2_mma, cudaFuncAttributeMaxDynamicSharedMemorySize, SMEM2);

    conv_x_kernel<<<480, 256>>>(X);
    conv_w1_kernel<<<32, 256>>>(W1);
    wsplit_kernel<<<32, 256>>>(W2);
    gemm1_mma<<<dim3(4, 60), 256, G1_SMEM>>>(b1);
    gemm2_mma<<<dim3(2, 8, NBT), 256, SMEM2>>>(b2, out);
    aux2_kernel<<<NBT, 256>>>(out + e_elems);
}

// round 6
// speedup vs baseline: 5.4861x; 1.1911x over previous
#include <cuda_runtime.h>
#include <cuda_fp16.h>
#include <cstdint>

// Problem constants: B=16, T=16 (Tm1=15), K=32, Do=128, H=256
#define NBT   240
#define NOBJ  32
#define DOBJ  128
#define NH    256
#define MROWS (NBT * NOBJ)   // 7680

// Scratch (fp16 U / V' = V + b1)
__device__ __align__(16) __half g_Uh[MROWS * NH];
__device__ __align__(16) __half g_Vh[MROWS * NH];
__device__ float g_S[MROWS];               // clipped per-object row sums
// fp16 SW128-swizzled images (each image = 128 rows x 64 halfs = 16KB)
__device__ __align__(16) unsigned char g_W2h[2 * 4 * 16384];   // [nh][4 k-imgs]
__device__ __align__(16) unsigned char g_Xh [60 * 2 * 16384];  // [mtile][2 k-imgs]
__device__ __align__(16) unsigned char g_W1h[4 * 2 * 16384];   // [ntile][2 k-imgs]

__device__ __forceinline__ uint32_t sw128(uint32_t off) { return off ^ ((off >> 3) & 0x70); }
__device__ __forceinline__ uint32_t smem_u32(const void* p) {
    uint32_t a;
    asm("{ .reg .u64 t; cvta.to.shared.u64 t, %1; cvt.u32.u64 %0, t; }" : "=r"(a) : "l"(p));
    return a;
}

#define LDSM_X4(r0, r1, r2, r3, addr) \
    asm volatile("ldmatrix.sync.aligned.m8n8.x4.shared.b16 {%0,%1,%2,%3}, [%4];" \
        : "=r"(r0), "=r"(r1), "=r"(r2), "=r"(r3) : "r"(addr))
#define MMA16816(d, a, b) \
    asm volatile("mma.sync.aligned.m16n8k16.row.col.f32.f16.f16.f32 " \
        "{%0,%1,%2,%3}, {%4,%5,%6,%7}, {%8,%9}, {%0,%1,%2,%3};" \
        : "+f"((d)[0]), "+f"((d)[1]), "+f"((d)[2]), "+f"((d)[3]) \
        : "r"((a)[0]), "r"((a)[1]), "r"((a)[2]), "r"((a)[3]), "r"((b)[0]), "r"((b)[1]))
#define CP_ASYNC16(dst, src) \
    asm volatile("cp.async.cg.shared.global [%0], [%1], 16;" :: "r"((uint32_t)(dst)), "l"(src))
#define CP_COMMIT() asm volatile("cp.async.commit_group;" ::: "memory")
#define CP_WAIT0()  asm volatile("cp.async.wait_group 0;" ::: "memory")

__device__ __forceinline__ uint32_t packh2(float x0, float x1) {
    __half2 h = __float22half2_rn(make_float2(x0, x1));
    return reinterpret_cast<uint32_t&>(h);
}
__device__ __forceinline__ uint32_t hadd_relu(uint32_t a, uint32_t b) {
    __half2 x = __hadd2(*reinterpret_cast<__half2*>(&a), *reinterpret_cast<__half2*>(&b));
    x = __hmax2(x, __float2half2_rn(0.0f));
    return reinterpret_cast<uint32_t&>(x);
}

// V smem stride: 280 halfs (560B, 16B-aligned, LDS.128 conflict-free)
#define VSTRIDE 280

// ---------------------------------------------------------------------------
// conv_x: gather X (rows t>=1) -> fp16 swizzled images; fused clipped row sums.
// ---------------------------------------------------------------------------
__global__ void conv_x_kernel(const float* __restrict__ X) {
    int idx = blockIdx.x * 256 + threadIdx.x;  // 0..122879
    int m  = idx >> 4;
    int g  = idx & 15;
    int kh = g >> 3, k8 = (g & 7) * 8;
    int bt = m >> 5, i = m & 31;
    int b  = bt / 15, t = bt - b * 15;
    const float* src = X + (size_t)((b * 16 + t + 1) * 32 + i) * DOBJ + kh * 64 + k8;
    float4 v0 = *(const float4*)(src);
    float4 v1 = *(const float4*)(src + 4);
    uint4 w;
    w.x = packh2(v0.x, v0.y); w.y = packh2(v0.z, v0.w);
    w.z = packh2(v1.x, v1.y); w.w = packh2(v1.z, v1.w);
    *(uint4*)(g_Xh + (m >> 7) * 32768 + kh * 16384 + sw128((uint32_t)((m & 127) * 128 + k8 * 2))) = w;
    float ssum = v0.x + v0.y + v0.z + v0.w + v1.x + v1.y + v1.z + v1.w;
#pragma unroll
    for (int off = 8; off >= 1; off >>= 1)
        ssum += __shfl_xor_sync(0xFFFFFFFF, ssum, off, 32);
    if (g == 0) g_S[m] = fminf(fmaxf(ssum, 0.0f), 1.0f);
}

// ---------------------------------------------------------------------------
// conv_w1: W1 -> fp16 swizzled images
// ---------------------------------------------------------------------------
__global__ void conv_w1_kernel(const float* __restrict__ W1) {
    int idx = blockIdx.x * 256 + threadIdx.x;  // 0..8191
    int op = idx >> 4;
    int g  = idx & 15;
    int kh = g >> 3, k8 = (g & 7) * 8;
    const float* src = W1 + (op & 255) * 256 + ((op >= 256) ? 128 : 0) + kh * 64 + k8;
    float4 v0 = *(const float4*)(src);
    float4 v1 = *(const float4*)(src + 4);
    uint4 w;
    w.x = packh2(v0.x, v0.y); w.y = packh2(v0.z, v0.w);
    w.z = packh2(v1.x, v1.y); w.w = packh2(v1.z, v1.w);
    int ntile = op >> 7, n = op & 127;
    *(uint4*)(g_W1h + ntile * 32768 + kh * 16384 + sw128((uint32_t)(n * 128 + k8 * 2))) = w;
}

// ---------------------------------------------------------------------------
// wsplit: W2 -> fp16 swizzled images
// ---------------------------------------------------------------------------
__global__ void wsplit_kernel(const float* __restrict__ W2) {
    int idx = blockIdx.x * 256 + threadIdx.x;
    int n   = idx >> 5;
    int g   = idx & 31;
    int c   = g >> 3;
    int k8  = (g & 7) * 8;
    const float* src = W2 + n * 256 + c * 64 + k8;
    float4 v0 = *(const float4*)(src);
    float4 v1 = *(const float4*)(src + 4);
    uint4 w;
    w.x = packh2(v0.x, v0.y); w.y = packh2(v0.z, v0.w);
    w.z = packh2(v1.x, v1.y); w.w = packh2(v1.z, v1.w);
    *(uint4*)(g_W2h + (n >> 7) * 65536 + c * 16384 + sw128((uint32_t)((n & 127) * 128 + k8 * 2))) = w;
}

// ---------------------------------------------------------------------------
// gemm1 via mma: grid (ntile 4, mtile 60), 256 thr. Epilogue -> fp16 U/V'.
// ---------------------------------------------------------------------------
#define G1_B    32768
#define G1_BIAS 65536
#define G1_SMEM 66048

__global__ __launch_bounds__(256, 2)
void gemm1_mma(const float* __restrict__ b1) {
    extern __shared__ __align__(1024) unsigned char smem[];
    const int tid = threadIdx.x, lane = tid & 31, wid = tid >> 5;
    const int ntile = blockIdx.x, mtile = blockIdx.y;
    const uint32_t sA = smem_u32(smem);
    const uint32_t sB = sA + G1_B;

    const uint4* gA = (const uint4*)(g_Xh)  + (size_t)mtile * 2048;
    const uint4* gB = (const uint4*)(g_W1h) + (size_t)ntile * 2048;
#pragma unroll
    for (int q = 0; q < 8; q++) {
        int s = tid + q * 256;
        CP_ASYNC16(sA + s * 16, gA + s);
        CP_ASYNC16(sB + s * 16, gB + s);
    }
    CP_COMMIT();
    if (ntile >= 2 && tid < 32)
        ((float4*)(smem + G1_BIAS))[tid] = ((const float4*)(b1 + (ntile - 2) * 128))[tid];
    CP_WAIT0();
    __syncthreads();

    float acc[2][8][4];
#pragma unroll
    for (int mt = 0; mt < 2; mt++)
#pragma unroll
        for (int nt = 0; nt < 8; nt++)
#pragma unroll
            for (int q = 0; q < 4; q++) acc[mt][nt][q] = 0.0f;

    const int m0w = (wid & 3) * 32;
    const int n0w = (wid >> 2) * 64;

#pragma unroll
    for (int ks = 0; ks < 8; ks++) {
        const int img = ks >> 2, kk = ks & 3;
        uint32_t afr[2][4], bfr[8][2];
        int abyte = kk * 32 + ((lane >> 4) << 4);
        int arow  = m0w + (lane & 15);
        uint32_t ab = sA + img * 16384;
        LDSM_X4(afr[0][0], afr[0][1], afr[0][2], afr[0][3], ab + sw128((uint32_t)(arow * 128 + abyte)));
        LDSM_X4(afr[1][0], afr[1][1], afr[1][2], afr[1][3], ab + sw128((uint32_t)((arow + 16) * 128 + abyte)));
        int nr  = n0w + ((lane >> 4) << 3) + (lane & 7);
        int kb2 = kk * 32 + (((lane >> 3) & 1) << 4);
        uint32_t bb = sB + img * 16384;
#pragma unroll
        for (int ntp = 0; ntp < 4; ntp++) {
            LDSM_X4(bfr[ntp * 2][0], bfr[ntp * 2][1],
                    bfr[ntp * 2 + 1][0], bfr[ntp * 2 + 1][1],
                    bb + sw128((uint32_t)((nr + ntp * 16) * 128 + kb2)));
        }
#pragma unroll
        for (int mt = 0; mt < 2; mt++)
#pragma unroll
            for (int nt = 0; nt < 8; nt++)
                MMA16816(acc[mt][nt], afr[mt], bfr[nt]);
    }

    const float* sBias = (const float*)(smem + G1_BIAS);
#pragma unroll
    for (int mt = 0; mt < 2; mt++) {
#pragma unroll
        for (int hp = 0; hp < 2; hp++) {
            int rl = m0w + mt * 16 + hp * 8 + (lane >> 2);
            int m  = mtile * 128 + rl;
#pragma unroll
            for (int nt = 0; nt < 8; nt++) {
                int nc = n0w + nt * 8 + (lane & 3) * 2;
                float ox = acc[mt][nt][hp * 2];
                float oy = acc[mt][nt][hp * 2 + 1];
                if (ntile < 2) {
                    *(uint32_t*)(g_Uh + (size_t)m * NH + ntile * 128 + nc) = packh2(ox, oy);
                } else {
                    *(uint32_t*)(g_Vh + (size_t)m * NH + (ntile - 2) * 128 + nc) =
                        packh2(ox + sBias[nc], oy + sBias[nc + 1]);
                }
            }
        }
    }
}

// ---------------------------------------------------------------------------
// gemm2 via mma: grid (nh 2, mtile 8, bt 240), 256 thr, CTA 128x128, K=256.
// fp16 staging, packed HADD2/HMAX2 gen-A.
// ---------------------------------------------------------------------------
#define OFF_A   0        // 2 images x 16KB
#define OFF_B   32768    // 2 images x 16KB
#define OFF_V   65536    // 32 x VSTRIDE halfs = 17920
#define OFF_U   83456    // 4 x 256 halfs = 2048
#define OFF_B2  85504    // 128 fp32 = 512
#define SMEM2   86016

__global__ __launch_bounds__(256, 2)
void gemm2_mma(const float* __restrict__ b2, float* __restrict__ out_e) {
    extern __shared__ __align__(1024) unsigned char smem[];
    const int tid = threadIdx.x, lane = tid & 31, wid = tid >> 5;
    const int nh = blockIdx.x, mtile = blockIdx.y, bt = blockIdx.z;

    __half* sVh = (__half*)(smem + OFF_V);
    __half* sUh = (__half*)(smem + OFF_U);
    float*  sb2 = (float*)(smem + OFF_B2);

    {   // stage V' (32x256 halfs -> stride VSTRIDE), U (4 rows), b2
        const uint4* Vg = (const uint4*)(g_Vh + (size_t)bt * NOBJ * NH);
#pragma unroll
        for (int q = 0; q < 4; q++) {
            int fidx = tid + q * 256;             // uint4 index (8 halfs each)
            uint4 v = Vg[fidx];
            int row = fidx >> 5, col8 = (fidx & 31) * 8;
            *(uint4*)(sVh + row * VSTRIDE + col8) = v;
        }
        if (tid < 128)
            ((uint4*)sUh)[tid] = ((const uint4*)(g_Uh + ((size_t)bt * NOBJ + mtile * 4) * NH))[tid];
        if (tid < 32) ((float4*)sb2)[tid] = ((const float4*)(b2 + nh * 128))[tid];
    }
    __syncthreads();

    const uint32_t sA = smem_u32(smem);
    const uint32_t sB = sA + OFF_B;

    float acc[2][8][4];
#pragma unroll
    for (int mt = 0; mt < 2; mt++)
#pragma unroll
        for (int nt = 0; nt < 8; nt++)
#pragma unroll
            for (int q = 0; q < 4; q++) acc[mt][nt][q] = 0.0f;

    const int m0w = (wid & 3) * 32;
    const int n0w = (wid >> 2) * 64;
    const int r  = tid & 127;
    const int kh = tid >> 7;
    const __half* u0 = sUh + (r >> 5) * 256 + kh * 64;    // warp-broadcast row
    const __half* v0 = sVh + (r & 31) * VSTRIDE + kh * 64; // conflict-free
    const uint4* gB = (const uint4*)(g_W2h + nh * 65536);

    for (int bc = 0; bc < 2; bc++) {
        if (bc) __syncthreads();
        // async copy B (2 images)
#pragma unroll
        for (int q = 0; q < 8; q++) {
            int s = tid + q * 256;
            CP_ASYNC16(sB + s * 16, gB + bc * 2048 + s);
        }
        CP_COMMIT();
        // generate A: 64 halfs (this thread's row slice in image kh)
        {
            const __half* u = u0 + bc * 128;
            const __half* v = v0 + bc * 128;
            uint32_t abase = sA + kh * 16384;
#pragma unroll
            for (int g = 0; g < 4; g++) {
                uint4 ua0 = *(const uint4*)(u + g * 16);
                uint4 ua1 = *(const uint4*)(u + g * 16 + 8);
                uint4 va0 = *(const uint4*)(v + g * 16);
                uint4 va1 = *(const uint4*)(v + g * 16 + 8);
                uint4 w0, w1;
                w0.x = hadd_relu(ua0.x, va0.x); w0.y = hadd_relu(ua0.y, va0.y);
                w0.z = hadd_relu(ua0.z, va0.z); w0.w = hadd_relu(ua0.w, va0.w);
                w1.x = hadd_relu(ua1.x, va1.x); w1.y = hadd_relu(ua1.y, va1.y);
                w1.z = hadd_relu(ua1.z, va1.z); w1.w = hadd_relu(ua1.w, va1.w);
                asm volatile("st.shared.v4.b32 [%0], {%1,%2,%3,%4};"
                    :: "r"(abase + sw128((uint32_t)(r * 128 + g * 32))),
                       "r"(w0.x), "r"(w0.y), "r"(w0.z), "r"(w0.w) : "memory");
                asm volatile("st.shared.v4.b32 [%0], {%1,%2,%3,%4};"
                    :: "r"(abase + sw128((uint32_t)(r * 128 + g * 32 + 16))),
                       "r"(w1.x), "r"(w1.y), "r"(w1.z), "r"(w1.w) : "memory");
            }
        }
        CP_WAIT0();
        __syncthreads();

#pragma unroll
        for (int ks = 0; ks < 8; ks++) {
            const int img = ks >> 2, kk = ks & 3;
            uint32_t afr[2][4], bfr[8][2];
            int abyte = kk * 32 + ((lane >> 4) << 4);
            int arow  = m0w + (lane & 15);
            uint32_t ab = sA + img * 16384;
            LDSM_X4(afr[0][0], afr[0][1], afr[0][2], afr[0][3], ab + sw128((uint32_t)(arow * 128 + abyte)));
            LDSM_X4(afr[1][0], afr[1][1], afr[1][2], afr[1][3], ab + sw128((uint32_t)((arow + 16) * 128 + abyte)));
            int nr  = n0w + ((lane >> 4) << 3) + (lane & 7);
            int kb2 = kk * 32 + (((lane >> 3) & 1) << 4);
            uint32_t bb = sB + img * 16384;
#pragma unroll
            for (int ntp = 0; ntp < 4; ntp++) {
                LDSM_X4(bfr[ntp * 2][0], bfr[ntp * 2][1],
                        bfr[ntp * 2 + 1][0], bfr[ntp * 2 + 1][1],
                        bb + sw128((uint32_t)((nr + ntp * 16) * 128 + kb2)));
            }
#pragma unroll
            for (int mt = 0; mt < 2; mt++)
#pragma unroll
                for (int nt = 0; nt < 8; nt++)
                    MMA16816(acc[mt][nt], afr[mt], bfr[nt]);
        }
    }

    // epilogue: e = relu(acc + b2)
    const size_t rowbase = (size_t)bt * 1024 + mtile * 128;
#pragma unroll
    for (int mt = 0; mt < 2; mt++) {
#pragma unroll
        for (int hp = 0; hp < 2; hp++) {
            int rl = m0w + mt * 16 + hp * 8 + (lane >> 2);
            float* dst = out_e + (rowbase + rl) * 256 + nh * 128 + (lane & 3) * 2;
#pragma unroll
            for (int nt = 0; nt < 8; nt++) {
                int nc = n0w + nt * 8 + (lane & 3) * 2;
                float2 o;
                o.x = fmaxf(acc[mt][nt][hp * 2]     + sb2[nc],     0.0f);
                o.y = fmaxf(acc[mt][nt][hp * 2 + 1] + sb2[nc + 1], 0.0f);
                *(float2*)(dst + n0w + nt * 8) = o;
            }
        }
    }
}

// ---------------------------------------------------------------------------
// aux2: all_is_obj from precomputed g_S
// ---------------------------------------------------------------------------
__global__ void aux2_kernel(float* __restrict__ out_a) {
    __shared__ float s[32];
    const int bt = blockIdx.x;
    const int tid = threadIdx.x;
    if (tid < 32) s[tid] = g_S[bt * 32 + tid];
    __syncthreads();
    const int t = bt - (bt / 15) * 15;
    float tc = (float)(t + 1);
#pragma unroll
    for (int q = 0; q < 4; q++) {
        int p = tid + q * 256;
        float v = s[p >> 5] * s[p & 31] * tc;
        out_a[(size_t)bt * 1024 + p] = fminf(fmaxf(v, 0.0f), 1.0f);
    }
}

// ---------------------------------------------------------------------------
extern "C" void kernel_launch(void* const* d_in, const int* in_sizes, int n_in,
                              void* d_out, int out_size) {
    const float* X  = (const float*)d_in[0];
    const float* W1 = (const float*)d_in[1];
    const float* b1 = (const float*)d_in[2];
    const float* W2 = (const float*)d_in[3];
    const float* b2 = (const float*)d_in[4];
    float* out = (float*)d_out;

    size_t e_elems = (size_t)out_size - (size_t)NBT * 1024;

    cudaFuncSetAttribute(gemm1_mma, cudaFuncAttributeMaxDynamicSharedMemorySize, G1_SMEM);
    cudaFuncSetAttribute(gemm2_mma, cudaFuncAttributeMaxDynamicSharedMemorySize, SMEM2);

    conv_x_kernel<<<480, 256>>>(X);
    conv_w1_kernel<<<32, 256>>>(W1);
    wsplit_kernel<<<32, 256>>>(W2);
    gemm1_mma<<<dim3(4, 60), 256, G1_SMEM>>>(b1);
    gemm2_mma<<<dim3(2, 8, NBT), 256, SMEM2>>>(b2, out);
    aux2_kernel<<<NBT, 256>>>(out + e_elems);
}

// round 7
// speedup vs baseline: 5.4962x; 1.0018x over previous
#include <cuda_runtime.h>
#include <cuda_fp16.h>
#include <cstdint>

// Problem constants: B=16, T=16 (Tm1=15), K=32, Do=128, H=256
#define NBT   240
#define NOBJ  32
#define DOBJ  128
#define NH    256
#define MROWS (NBT * NOBJ)   // 7680

// Scratch (fp16 U / V' = V + b1)
__device__ __align__(16) __half g_Uh[MROWS * NH];
__device__ __align__(16) __half g_Vh[MROWS * NH];
__device__ float g_S[MROWS];
// fp16 SW128-swizzled images (image = 128 rows x 64 halfs = 16KB)
__device__ __align__(16) unsigned char g_W2h[2 * 4 * 16384];   // [nh][4 k-imgs]
__device__ __align__(16) unsigned char g_Xh [60 * 2 * 16384];  // [mtile][2 k-imgs]
__device__ __align__(16) unsigned char g_W1h[4 * 2 * 16384];   // [ntile][2 k-imgs]

__device__ __forceinline__ uint32_t sw128(uint32_t off) { return off ^ ((off >> 3) & 0x70); }
__device__ __forceinline__ uint32_t smem_u32(const void* p) {
    uint32_t a;
    asm("{ .reg .u64 t; cvta.to.shared.u64 t, %1; cvt.u32.u64 %0, t; }" : "=r"(a) : "l"(p));
    return a;
}

#define LDSM_X4(r0, r1, r2, r3, addr) \
    asm volatile("ldmatrix.sync.aligned.m8n8.x4.shared.b16 {%0,%1,%2,%3}, [%4];" \
        : "=r"(r0), "=r"(r1), "=r"(r2), "=r"(r3) : "r"(addr))
#define MMA16816(d, a, b) \
    asm volatile("mma.sync.aligned.m16n8k16.row.col.f32.f16.f16.f32 " \
        "{%0,%1,%2,%3}, {%4,%5,%6,%7}, {%8,%9}, {%0,%1,%2,%3};" \
        : "+f"((d)[0]), "+f"((d)[1]), "+f"((d)[2]), "+f"((d)[3]) \
        : "r"((a)[0]), "r"((a)[1]), "r"((a)[2]), "r"((a)[3]), "r"((b)[0]), "r"((b)[1]))
#define CP_ASYNC16(dst, src) \
    asm volatile("cp.async.cg.shared.global [%0], [%1], 16;" :: "r"((uint32_t)(dst)), "l"(src))
#define CP_COMMIT() asm volatile("cp.async.commit_group;" ::: "memory")
#define CP_WAIT0()  asm volatile("cp.async.wait_group 0;" ::: "memory")

__device__ __forceinline__ uint32_t packh2(float x0, float x1) {
    __half2 h = __float22half2_rn(make_float2(x0, x1));
    return reinterpret_cast<uint32_t&>(h);
}
__device__ __forceinline__ uint32_t hadd_relu(uint32_t a, uint32_t b) {
    __half2 x = __hadd2(*reinterpret_cast<__half2*>(&a), *reinterpret_cast<__half2*>(&b));
    x = __hmax2(x, __float2half2_rn(0.0f));
    return reinterpret_cast<uint32_t&>(x);
}

#define VSTRIDE 280   // halfs; 560B rows, 16B-aligned, LDS.128 conflict-free

// ---------------------------------------------------------------------------
// conv_x: gather X (rows t>=1) -> fp16 swizzled images; fused clipped row sums.
// ---------------------------------------------------------------------------
__global__ void conv_x_kernel(const float* __restrict__ X) {
    int idx = blockIdx.x * 256 + threadIdx.x;
    int m  = idx >> 4;
    int g  = idx & 15;
    int kh = g >> 3, k8 = (g & 7) * 8;
    int bt = m >> 5, i = m & 31;
    int b  = bt / 15, t = bt - b * 15;
    const float* src = X + (size_t)((b * 16 + t + 1) * 32 + i) * DOBJ + kh * 64 + k8;
    float4 v0 = *(const float4*)(src);
    float4 v1 = *(const float4*)(src + 4);
    uint4 w;
    w.x = packh2(v0.x, v0.y); w.y = packh2(v0.z, v0.w);
    w.z = packh2(v1.x, v1.y); w.w = packh2(v1.z, v1.w);
    *(uint4*)(g_Xh + (m >> 7) * 32768 + kh * 16384 + sw128((uint32_t)((m & 127) * 128 + k8 * 2))) = w;
    float ssum = v0.x + v0.y + v0.z + v0.w + v1.x + v1.y + v1.z + v1.w;
#pragma unroll
    for (int off = 8; off >= 1; off >>= 1)
        ssum += __shfl_xor_sync(0xFFFFFFFF, ssum, off, 32);
    if (g == 0) g_S[m] = fminf(fmaxf(ssum, 0.0f), 1.0f);
}

// ---------------------------------------------------------------------------
// conv_w1: W1 -> fp16 swizzled images
// ---------------------------------------------------------------------------
__global__ void conv_w1_kernel(const float* __restrict__ W1) {
    int idx = blockIdx.x * 256 + threadIdx.x;
    int op = idx >> 4;
    int g  = idx & 15;
    int kh = g >> 3, k8 = (g & 7) * 8;
    const float* src = W1 + (op & 255) * 256 + ((op >= 256) ? 128 : 0) + kh * 64 + k8;
    float4 v0 = *(const float4*)(src);
    float4 v1 = *(const float4*)(src + 4);
    uint4 w;
    w.x = packh2(v0.x, v0.y); w.y = packh2(v0.z, v0.w);
    w.z = packh2(v1.x, v1.y); w.w = packh2(v1.z, v1.w);
    int ntile = op >> 7, n = op & 127;
    *(uint4*)(g_W1h + ntile * 32768 + kh * 16384 + sw128((uint32_t)(n * 128 + k8 * 2))) = w;
}

// ---------------------------------------------------------------------------
// wsplit: W2 -> fp16 swizzled images  [nh][kimg c]
// ---------------------------------------------------------------------------
__global__ void wsplit_kernel(const float* __restrict__ W2) {
    int idx = blockIdx.x * 256 + threadIdx.x;
    int n   = idx >> 5;
    int g   = idx & 31;
    int c   = g >> 3;
    int k8  = (g & 7) * 8;
    const float* src = W2 + n * 256 + c * 64 + k8;
    float4 v0 = *(const float4*)(src);
    float4 v1 = *(const float4*)(src + 4);
    uint4 w;
    w.x = packh2(v0.x, v0.y); w.y = packh2(v0.z, v0.w);
    w.z = packh2(v1.x, v1.y); w.w = packh2(v1.z, v1.w);
    *(uint4*)(g_W2h + (n >> 7) * 65536 + c * 16384 + sw128((uint32_t)((n & 127) * 128 + k8 * 2))) = w;
}

// ---------------------------------------------------------------------------
// gemm1 via mma: grid (ntile 4, mtile 60), 256 thr. Epilogue -> fp16 U/V'.
// ---------------------------------------------------------------------------
#define G1_B    32768
#define G1_BIAS 65536
#define G1_SMEM 66048

__global__ __launch_bounds__(256, 2)
void gemm1_mma(const float* __restrict__ b1) {
    extern __shared__ __align__(1024) unsigned char smem[];
    const int tid = threadIdx.x, lane = tid & 31, wid = tid >> 5;
    const int ntile = blockIdx.x, mtile = blockIdx.y;
    const uint32_t sA = smem_u32(smem);
    const uint32_t sB = sA + G1_B;

    const uint4* gA = (const uint4*)(g_Xh)  + (size_t)mtile * 2048;
    const uint4* gB = (const uint4*)(g_W1h) + (size_t)ntile * 2048;
#pragma unroll
    for (int q = 0; q < 8; q++) {
        int s = tid + q * 256;
        CP_ASYNC16(sA + s * 16, gA + s);
        CP_ASYNC16(sB + s * 16, gB + s);
    }
    CP_COMMIT();
    if (ntile >= 2 && tid < 32)
        ((float4*)(smem + G1_BIAS))[tid] = ((const float4*)(b1 + (ntile - 2) * 128))[tid];
    CP_WAIT0();
    __syncthreads();

    float acc[2][8][4];
#pragma unroll
    for (int mt = 0; mt < 2; mt++)
#pragma unroll
        for (int nt = 0; nt < 8; nt++)
#pragma unroll
            for (int q = 0; q < 4; q++) acc[mt][nt][q] = 0.0f;

    const int m0w = (wid & 3) * 32;
    const int n0w = (wid >> 2) * 64;

#pragma unroll
    for (int ks = 0; ks < 8; ks++) {
        const int img = ks >> 2, kk = ks & 3;
        uint32_t afr[2][4], bfr[8][2];
        int abyte = kk * 32 + ((lane >> 4) << 4);
        int arow  = m0w + (lane & 15);
        uint32_t ab = sA + img * 16384;
        LDSM_X4(afr[0][0], afr[0][1], afr[0][2], afr[0][3], ab + sw128((uint32_t)(arow * 128 + abyte)));
        LDSM_X4(afr[1][0], afr[1][1], afr[1][2], afr[1][3], ab + sw128((uint32_t)((arow + 16) * 128 + abyte)));
        int nr  = n0w + ((lane >> 4) << 3) + (lane & 7);
        int kb2 = kk * 32 + (((lane >> 3) & 1) << 4);
        uint32_t bb = sB + img * 16384;
#pragma unroll
        for (int ntp = 0; ntp < 4; ntp++) {
            LDSM_X4(bfr[ntp * 2][0], bfr[ntp * 2][1],
                    bfr[ntp * 2 + 1][0], bfr[ntp * 2 + 1][1],
                    bb + sw128((uint32_t)((nr + ntp * 16) * 128 + kb2)));
        }
#pragma unroll
        for (int mt = 0; mt < 2; mt++)
#pragma unroll
            for (int nt = 0; nt < 8; nt++)
                MMA16816(acc[mt][nt], afr[mt], bfr[nt]);
    }

    const float* sBias = (const float*)(smem + G1_BIAS);
#pragma unroll
    for (int mt = 0; mt < 2; mt++) {
#pragma unroll
        for (int hp = 0; hp < 2; hp++) {
            int rl = m0w + mt * 16 + hp * 8 + (lane >> 2);
            int m  = mtile * 128 + rl;
#pragma unroll
            for (int nt = 0; nt < 8; nt++) {
                int nc = n0w + nt * 8 + (lane & 3) * 2;
                float ox = acc[mt][nt][hp * 2];
                float oy = acc[mt][nt][hp * 2 + 1];
                if (ntile < 2) {
                    *(uint32_t*)(g_Uh + (size_t)m * NH + ntile * 128 + nc) = packh2(ox, oy);
                } else {
                    *(uint32_t*)(g_Vh + (size_t)m * NH + (ntile - 2) * 128 + nc) =
                        packh2(ox + sBias[nc], oy + sBias[nc + 1]);
                }
            }
        }
    }
}

// ---------------------------------------------------------------------------
// gemm2 full-N: grid (mtile 8, bt 240), 512 thr (16 warps).
// CTA tile: 128 pairs x 256 outputs, K=256 fully resident.
// SMEM: A 4 imgs (64KB) | B 8 imgs = whole W2h (128KB) | V | U | b2
// ---------------------------------------------------------------------------
#define OFF_A   0
#define OFF_B   65536
#define OFF_V   196608   // 32 x VSTRIDE halfs = 17920
#define OFF_U   214528   // 4 x 256 halfs = 2048
#define OFF_B2  216576   // 256 fp32 = 1024
#define SMEM2   217600

__global__ __launch_bounds__(512, 1)
void gemm2_mma(const float* __restrict__ b2, float* __restrict__ out_e) {
    extern __shared__ __align__(1024) unsigned char smem[];
    const int tid = threadIdx.x, lane = tid & 31, wid = tid >> 5;
    const int mtile = blockIdx.x, bt = blockIdx.y;

    __half* sVh = (__half*)(smem + OFF_V);
    __half* sUh = (__half*)(smem + OFF_U);
    float*  sb2 = (float*)(smem + OFF_B2);

    const uint32_t sA = smem_u32(smem);
    const uint32_t sB = sA + OFF_B;

    // Kick off B copy (whole W2h, 128KB, L2-resident) immediately
    {
        const uint4* gB = (const uint4*)(g_W2h);
#pragma unroll
        for (int q = 0; q < 16; q++) {
            int s = tid + q * 512;
            CP_ASYNC16(sB + s * 16, gB + s);
        }
        CP_COMMIT();
    }
    // Stage V' (32 rows -> stride VSTRIDE), U (4 rows), b2 (256)
    {
        const uint4* Vg = (const uint4*)(g_Vh + (size_t)bt * NOBJ * NH);
#pragma unroll
        for (int q = 0; q < 2; q++) {
            int fidx = tid + q * 512;             // uint4 index (8 halfs)
            uint4 v = Vg[fidx];
            int row = fidx >> 5, col8 = (fidx & 31) * 8;
            *(uint4*)(sVh + row * VSTRIDE + col8) = v;
        }
        if (tid < 128)
            ((uint4*)sUh)[tid] = ((const uint4*)(g_Uh + ((size_t)bt * NOBJ + mtile * 4) * NH))[tid];
        if (tid < 64) ((float4*)sb2)[tid] = ((const float4*)b2)[tid];
    }
    __syncthreads();

    // Generate A: whole 128x256 h tile, once. thread -> (row r, k-quarter kq)
    {
        const int r  = tid & 127;
        const int kq = tid >> 7;                  // 0..3
        const __half* u = sUh + (r >> 5) * 256 + kq * 64;
        const __half* v = sVh + (r & 31) * VSTRIDE + kq * 64;
        uint32_t abase = sA + kq * 16384;
#pragma unroll
        for (int g = 0; g < 4; g++) {
            uint4 ua0 = *(const uint4*)(u + g * 16);
            uint4 ua1 = *(const uint4*)(u + g * 16 + 8);
            uint4 va0 = *(const uint4*)(v + g * 16);
            uint4 va1 = *(const uint4*)(v + g * 16 + 8);
            uint4 w0, w1;
            w0.x = hadd_relu(ua0.x, va0.x); w0.y = hadd_relu(ua0.y, va0.y);
            w0.z = hadd_relu(ua0.z, va0.z); w0.w = hadd_relu(ua0.w, va0.w);
            w1.x = hadd_relu(ua1.x, va1.x); w1.y = hadd_relu(ua1.y, va1.y);
            w1.z = hadd_relu(ua1.z, va1.z); w1.w = hadd_relu(ua1.w, va1.w);
            asm volatile("st.shared.v4.b32 [%0], {%1,%2,%3,%4};"
                :: "r"(abase + sw128((uint32_t)(r * 128 + g * 32))),
                   "r"(w0.x), "r"(w0.y), "r"(w0.z), "r"(w0.w) : "memory");
            asm volatile("st.shared.v4.b32 [%0], {%1,%2,%3,%4};"
                :: "r"(abase + sw128((uint32_t)(r * 128 + g * 32 + 16))),
                   "r"(w1.x), "r"(w1.y), "r"(w1.z), "r"(w1.w) : "memory");
        }
    }
    CP_WAIT0();
    __syncthreads();

    float acc[2][8][4];
#pragma unroll
    for (int mt = 0; mt < 2; mt++)
#pragma unroll
        for (int nt = 0; nt < 8; nt++)
#pragma unroll
            for (int q = 0; q < 4; q++) acc[mt][nt][q] = 0.0f;

    const int m0w = (wid & 3) * 32;           // 4 warps over M=128
    const int n0w = (wid >> 2) * 64;          // 4 warps over N=256
    const uint32_t bblk = sB + (uint32_t)(n0w >> 7) * 65536;  // nh block
    const int nloc = n0w & 127;

    // Straight burst: 16 k-steps, no syncs
#pragma unroll
    for (int ks = 0; ks < 16; ks++) {
        const int img = ks >> 2, kk = ks & 3;
        uint32_t afr[2][4], bfr[8][2];
        int abyte = kk * 32 + ((lane >> 4) << 4);
        int arow  = m0w + (lane & 15);
        uint32_t ab = sA + img * 16384;
        LDSM_X4(afr[0][0], afr[0][1], afr[0][2], afr[0][3], ab + sw128((uint32_t)(arow * 128 + abyte)));
        LDSM_X4(afr[1][0], afr[1][1], afr[1][2], afr[1][3], ab + sw128((uint32_t)((arow + 16) * 128 + abyte)));
        int nr  = nloc + ((lane >> 4) << 3) + (lane & 7);
        int kb2 = kk * 32 + (((lane >> 3) & 1) << 4);
        uint32_t bb = bblk + img * 16384;
#pragma unroll
        for (int ntp = 0; ntp < 4; ntp++) {
            LDSM_X4(bfr[ntp * 2][0], bfr[ntp * 2][1],
                    bfr[ntp * 2 + 1][0], bfr[ntp * 2 + 1][1],
                    bb + sw128((uint32_t)((nr + ntp * 16) * 128 + kb2)));
        }
#pragma unroll
        for (int mt = 0; mt < 2; mt++)
#pragma unroll
            for (int nt = 0; nt < 8; nt++)
                MMA16816(acc[mt][nt], afr[mt], bfr[nt]);
    }

    // Epilogue: e = relu(acc + b2)
    const size_t rowbase = (size_t)bt * 1024 + mtile * 128;
#pragma unroll
    for (int mt = 0; mt < 2; mt++) {
#pragma unroll
        for (int hp = 0; hp < 2; hp++) {
            int rl = m0w + mt * 16 + hp * 8 + (lane >> 2);
            float* dst = out_e + (rowbase + rl) * 256 + (lane & 3) * 2;
#pragma unroll
            for (int nt = 0; nt < 8; nt++) {
                int nc = n0w + nt * 8 + (lane & 3) * 2;
                float2 o;
                o.x = fmaxf(acc[mt][nt][hp * 2]     + sb2[nc],     0.0f);
                o.y = fmaxf(acc[mt][nt][hp * 2 + 1] + sb2[nc + 1], 0.0f);
                *(float2*)(dst + n0w + nt * 8) = o;
            }
        }
    }
}

// ---------------------------------------------------------------------------
// aux2: all_is_obj from precomputed g_S
// ---------------------------------------------------------------------------
__global__ void aux2_kernel(float* __restrict__ out_a) {
    __shared__ float s[32];
    const int bt = blockIdx.x;
    const int tid = threadIdx.x;
    if (tid < 32) s[tid] = g_S[bt * 32 + tid];
    __syncthreads();
    const int t = bt - (bt / 15) * 15;
    float tc = (float)(t + 1);
#pragma unroll
    for (int q = 0; q < 4; q++) {
        int p = tid + q * 256;
        float v = s[p >> 5] * s[p & 31] * tc;
        out_a[(size_t)bt * 1024 + p] = fminf(fmaxf(v, 0.0f), 1.0f);
    }
}

// ---------------------------------------------------------------------------
extern "C" void kernel_launch(void* const* d_in, const int* in_sizes, int n_in,
                              void* d_out, int out_size) {
    const float* X  = (const float*)d_in[0];
    const float* W1 = (const float*)d_in[1];
    const float* b1 = (const float*)d_in[2];
    const float* W2 = (const float*)d_in[3];
    const float* b2 = (const float*)d_in[4];
    float* out = (float*)d_out;

    size_t e_elems = (size_t)out_size - (size_t)NBT * 1024;

    cudaFuncSetAttribute(gemm1_mma, cudaFuncAttributeMaxDynamicSharedMemorySize, G1_SMEM);
    cudaFuncSetAttribute(gemm2_mma, cudaFuncAttributeMaxDynamicSharedMemorySize, SMEM2);

    conv_x_kernel<<<480, 256>>>(X);
    conv_w1_kernel<<<32, 256>>>(W1);
    wsplit_kernel<<<32, 256>>>(W2);
    gemm1_mma<<<dim3(4, 60), 256, G1_SMEM>>>(b1);
    gemm2_mma<<<dim3(8, NBT), 512, SMEM2>>>(b2, out);
    aux2_kernel<<<NBT, 256>>>(out + e_elems);
}